// round 9
// baseline (speedup 1.0000x reference)
#include <cuda_runtime.h>

#define NT 512
typedef unsigned long long u64;
typedef unsigned int u32;

static constexpr int L = 64, D = 128, H = 8, DK = 16;

// smem float offsets
static constexpr int O_XQ  = 0;      // [64][132] xq (padded A)
static constexpr int O_XK  = 8448;   // [64][132] xk -> CTB (stride 132)
static constexpr int O_Q   = 16896;  // [64][128] Q -> TVB
static constexpr int O_V   = 25088;  // [64][128] V
static constexpr int O_KT  = 33280;  // [128][64] K transposed (rotated)
static constexpr int O_WB0 = 41472;  // [64][128] W chunk buf 0
static constexpr int O_WB1 = 49664;  // [64][128] W chunk buf 1
static constexpr int O_S0  = 41472;  // [64][68]  (overlaps WB, disjoint in time)
static constexpr int O_S1  = 45824;  // [64][68]
static constexpr int SM_FLOATS = 57856;
static constexpr int SM_BYTES  = SM_FLOATS * 4;  // 231424

static __device__ __forceinline__ u64 pk2(float lo, float hi) {
    u64 r; asm("mov.b64 %0,{%1,%2};" : "=l"(r) : "f"(lo), "f"(hi)); return r;
}
static __device__ __forceinline__ u64 dup2(float v) {
    u64 r; asm("mov.b64 %0,{%1,%1};" : "=l"(r) : "f"(v)); return r;
}
static __device__ __forceinline__ void fma2(u64& d, u64 a, u64 b) {
    asm("fma.rn.f32x2 %0, %1, %2, %0;" : "+l"(d) : "l"(a), "l"(b));
}
static __device__ __forceinline__ float2 upk(u64 v) {
    float lo, hi; asm("mov.b64 {%0,%1}, %2;" : "=f"(lo), "=f"(hi) : "l"(v));
    return make_float2(lo, hi);
}

static __device__ __forceinline__ void cpa16(float* dst, const float* src) {
    u32 d = (u32)__cvta_generic_to_shared(dst);
    asm volatile("cp.async.cg.shared.global [%0], [%1], 16;" :: "r"(d), "l"(src));
}
static __device__ __forceinline__ void cpa_commit() {
    asm volatile("cp.async.commit_group;");
}
template<int N> static __device__ __forceinline__ void cpa_wait() {
    asm volatile("cp.async.wait_group %0;" :: "n"(N));
}
static __device__ __forceinline__ void half_bar(int hsel) {
    asm volatile("bar.sync %0, %1;" :: "r"(hsel + 1), "r"(256) : "memory");
}
// stage one 64x128 weight chunk (32KB) as one cp.async group
static __device__ __forceinline__ void stage_w(float* dst, const float* src, int tid) {
    for (int i = tid; i < 2048; i += NT) cpa16(dst + 4 * i, src + 4 * i);
    cpa_commit();
}

// 2D-layout half-GEMM: 4 interleaved rows (r0 + 4i) x 4 cols. A stride 132 (padded).
static __device__ __forceinline__ void hg2d(const float* __restrict__ A,
                                            const float* __restrict__ wb,
                                            int r0, int c0, int kb, u64 acc[4][2])
{
#pragma unroll 2
    for (int kk = 0; kk < 16; ++kk) {
        float4 a[4];
#pragma unroll
        for (int i = 0; i < 4; i++)
            a[i] = *reinterpret_cast<const float4*>(A + (r0 + 4 * i) * 132 + kb + 4 * kk);
#pragma unroll
        for (int j = 0; j < 4; j++) {
            float4 b = *reinterpret_cast<const float4*>(wb + (4 * kk + j) * 128 + c0);
            u64 b0 = pk2(b.x, b.y), b1 = pk2(b.z, b.w);
#pragma unroll
            for (int i = 0; i < 4; i++) {
                float av = (j == 0) ? a[i].x : (j == 1) ? a[i].y : (j == 2) ? a[i].z : a[i].w;
                u64 ad = dup2(av);
                fma2(acc[i][0], ad, b0);
                fma2(acc[i][1], ad, b1);
            }
        }
    }
}

// old-layout half-GEMM, 8 contiguous rows x 2 packed cols (used for K: transpose-friendly).
template<int AS>
static __device__ __forceinline__ void hg82(const float* __restrict__ A,
                                            const float* __restrict__ wb,
                                            int r0, int c0, int kb, u64 acc[8])
{
#pragma unroll 2
    for (int kk = 0; kk < 16; ++kk) {
        float4 a[8];
#pragma unroll
        for (int i = 0; i < 8; i++)
            a[i] = *reinterpret_cast<const float4*>(A + (r0 + i) * AS + kb + 4 * kk);
#pragma unroll
        for (int j = 0; j < 4; j++) {
            u64 b = *reinterpret_cast<const u64*>(wb + (4 * kk + j) * 128 + c0);
#pragma unroll
            for (int i = 0; i < 8; i++) {
                float av = (j == 0) ? a[i].x : (j == 1) ? a[i].y : (j == 2) ? a[i].z : a[i].w;
                fma2(acc[i], dup2(av), b);
            }
        }
    }
}

// epilogue half-GEMM, 4 rows x 4 cols, warp spans full row (for shuffle-LN).
template<int AS>
static __device__ __forceinline__ void hg44(const float* __restrict__ A,
                                            const float* __restrict__ wb,
                                            int r0, int c0, int kb, u64 acc[4][2])
{
#pragma unroll 2
    for (int kk = 0; kk < 16; ++kk) {
        float4 a[4];
#pragma unroll
        for (int i = 0; i < 4; i++)
            a[i] = *reinterpret_cast<const float4*>(A + (r0 + i) * AS + kb + 4 * kk);
#pragma unroll
        for (int j = 0; j < 4; j++) {
            float4 b = *reinterpret_cast<const float4*>(wb + (4 * kk + j) * 128 + c0);
            u64 b0 = pk2(b.x, b.y), b1 = pk2(b.z, b.w);
#pragma unroll
            for (int i = 0; i < 4; i++) {
                float av = (j == 0) ? a[i].x : (j == 1) ? a[i].y : (j == 2) ? a[i].z : a[i].w;
                u64 ad = dup2(av);
                fma2(acc[i][0], ad, b0);
                fma2(acc[i][1], ad, b1);
            }
        }
    }
}

__global__ void __launch_bounds__(NT, 1)
fused_attn_kernel(const float* __restrict__ xq_g, const float* __restrict__ xk_g,
                  const float* __restrict__ xt_g,
                  const float* __restrict__ Wq,  const float* __restrict__ bq,
                  const float* __restrict__ Wk,  const float* __restrict__ bk,
                  const float* __restrict__ Wv,  const float* __restrict__ bv,
                  const float* __restrict__ Wot, const float* __restrict__ bot,
                  const float* __restrict__ Wtg, const float* __restrict__ btg,
                  const float* __restrict__ g_time, const float* __restrict__ b_time,
                  const float* __restrict__ g_tgt,  const float* __restrict__ b_tgt,
                  float* __restrict__ out, int BN)
{
    extern __shared__ float sm[];
    const int bn = blockIdx.x, tid = threadIdx.x;

    const float* xq_src = xq_g + (size_t)bn * (L * D);
    const float* xk_src = xk_g + (size_t)bn * (L * D);
    const float* xt_src = xt_g + (size_t)bn * (L * D);

    const size_t attnElems = (size_t)BN * H * (L * L);
    float* tv_base = out + attnElems + (size_t)bn * (L * D);
    float* ct_base = out + attnElems + (size_t)BN * (L * D) + (size_t)bn * (L * D);

    // 2D GEMM mapping
    const int warp = tid >> 5, lane = tid & 31;
    const int wr = warp & 3, wc = warp >> 2;
    const int rg = lane & 3, cf = lane >> 2;
    const int r0n = wr * 16 + rg;           // rows r0n + 4i
    const int c0n = wc * 32 + cf * 4;
    // K-GEMM old mapping: 8 contiguous rows x 2 cols
    const int r0a = 8 * (tid >> 6);
    const int c0a = 2 * (tid & 63);
    // epilogue mapping: 4 rows x 4 cols, warp spans a full row
    const int r0e = 4 * warp;
    const int c0e = 4 * lane;

    float* WB0 = sm + O_WB0;
    float* WB1 = sm + O_WB1;

    // ---- group0: xq, xk (padded), Wq.h0 ; group1: Wq.h1 ----
    for (int i = tid; i < 2048; i += NT) {
        int row = i >> 5, c4 = (i & 31) * 4;
        cpa16(sm + O_XQ + row * 132 + c4, xq_src + 4 * i);
        cpa16(sm + O_XK + row * 132 + c4, xk_src + 4 * i);
        cpa16(WB0 + 4 * i, Wq + 4 * i);
    }
    cpa_commit();
    stage_w(WB1, Wq + 8192, tid);

    // ================= Q = xq @ Wq + bq (2D layout) =================
    cpa_wait<1>(); __syncthreads();
    {
        u64 acc[4][2];
        float4 bb = __ldg(reinterpret_cast<const float4*>(bq + c0n));
        u64 b0 = pk2(bb.x, bb.y), b1 = pk2(bb.z, bb.w);
#pragma unroll
        for (int i = 0; i < 4; i++) { acc[i][0] = b0; acc[i][1] = b1; }
        hg2d(sm + O_XQ, WB0, r0n, c0n, 0, acc);
        __syncthreads();
        stage_w(WB0, Wk, tid);
        cpa_wait<1>(); __syncthreads();
        hg2d(sm + O_XQ, WB1, r0n, c0n, 64, acc);
#pragma unroll
        for (int i = 0; i < 4; i++) {
            float2 p0 = upk(acc[i][0]), p1 = upk(acc[i][1]);
            *reinterpret_cast<float4*>(sm + O_Q + (r0n + 4 * i) * 128 + c0n) =
                make_float4(p0.x, p0.y, p1.x, p1.y);
        }
    }
    __syncthreads();
    stage_w(WB1, Wk + 8192, tid);

    // ================= K = xk @ Wk + bk -> KT[128][64] rotated =================
    cpa_wait<1>(); __syncthreads();
    {
        u64 acc8[8];
        float2 bb = *reinterpret_cast<const float2*>(bk + c0a);
        u64 bi = pk2(bb.x, bb.y);
#pragma unroll
        for (int i = 0; i < 8; i++) acc8[i] = bi;
        hg82<132>(sm + O_XK, WB0, r0a, c0a, 0, acc8);
        __syncthreads();
        stage_w(WB0, Wv, tid);
        cpa_wait<1>(); __syncthreads();
        hg82<132>(sm + O_XK, WB1, r0a, c0a, 64, acc8);
        float va[2][8];
#pragma unroll
        for (int i = 0; i < 8; i++) {
            float2 p = upk(acc8[i]);
            va[0][i] = p.x; va[1][i] = p.y;
        }
#pragma unroll
        for (int cc = 0; cc < 2; ++cc) {
            int c = c0a + cc;
            int rot = (4 * (c >> 1)) & 63;
            *reinterpret_cast<float4*>(sm + O_KT + c * 64 + ((r0a + rot) & 63)) =
                make_float4(va[cc][0], va[cc][1], va[cc][2], va[cc][3]);
            *reinterpret_cast<float4*>(sm + O_KT + c * 64 + ((r0a + 4 + rot) & 63)) =
                make_float4(va[cc][4], va[cc][5], va[cc][6], va[cc][7]);
        }
    }
    __syncthreads();
    stage_w(WB1, Wv + 8192, tid);

    // ================= V = xk @ Wv + bv (2D layout) =================
    cpa_wait<1>(); __syncthreads();
    {
        u64 acc[4][2];
        float4 bb = __ldg(reinterpret_cast<const float4*>(bv + c0n));
        u64 b0 = pk2(bb.x, bb.y), b1 = pk2(bb.z, bb.w);
#pragma unroll
        for (int i = 0; i < 4; i++) { acc[i][0] = b0; acc[i][1] = b1; }
        hg2d(sm + O_XK, WB0, r0n, c0n, 0, acc);
        cpa_wait<0>(); __syncthreads();
        hg2d(sm + O_XK, WB1, r0n, c0n, 64, acc);
#pragma unroll
        for (int i = 0; i < 4; i++) {
            float2 p0 = upk(acc[i][0]), p1 = upk(acc[i][1]);
            *reinterpret_cast<float4*>(sm + O_V + (r0n + 4 * i) * 128 + c0n) =
                make_float4(p0.x, p0.y, p1.x, p1.y);
        }
    }
    __syncthreads();

    // ================= per head-pair: scores then apply (half-barriers) ======
    const int t = tid & 255, hsel = tid >> 8;
#pragma unroll 1
    for (int p = 0; p < 4; ++p) {
        const int h = 2 * p + hsel;
        // ---- S_h = Q_h @ K_h^T * 0.25 ----
        {
            const int brg = t >> 4, bcg = t & 15;
            u64 acc[4][2];
#pragma unroll
            for (int i = 0; i < 4; i++) acc[i][0] = acc[i][1] = 0ull;
#pragma unroll
            for (int kk = 0; kk < 4; ++kk) {
                float av[4][4];
#pragma unroll
                for (int i = 0; i < 4; i++) {
                    float4 a = *reinterpret_cast<const float4*>(
                        sm + O_Q + (4 * brg + i) * 128 + h * DK + 4 * kk);
                    av[i][0] = a.x; av[i][1] = a.y; av[i][2] = a.z; av[i][3] = a.w;
                }
#pragma unroll
                for (int j = 0; j < 4; j++) {
                    int c = h * DK + 4 * kk + j;
                    int rot = (4 * (c >> 1)) & 63;
                    float4 b = *reinterpret_cast<const float4*>(
                        sm + O_KT + c * 64 + ((4 * bcg + rot) & 63));
                    u64 b0 = pk2(b.x, b.y), b1 = pk2(b.z, b.w);
#pragma unroll
                    for (int i = 0; i < 4; i++) {
                        u64 ad = dup2(av[i][j]);
                        fma2(acc[i][0], ad, b0);
                        fma2(acc[i][1], ad, b1);
                    }
                }
            }
            float* Sh = sm + (hsel ? O_S1 : O_S0);
            float* attn = out + ((size_t)bn * H + h) * (L * L);
#pragma unroll
            for (int i = 0; i < 4; i++) {
                float2 p0 = upk(acc[i][0]), p1 = upk(acc[i][1]);
                float4 v = make_float4(p0.x * 0.25f, p0.y * 0.25f, p1.x * 0.25f, p1.y * 0.25f);
                *reinterpret_cast<float4*>(Sh + (4 * brg + i) * 68 + 4 * bcg) = v;
                *reinterpret_cast<float4*>(attn + (4 * brg + i) * L + 4 * bcg) = v;
            }
        }
        half_bar(hsel);
        // ---- TV_h = S_h @ V_h (sel 0) ; CT_h = S_h @ XT_h-global (sel 1) ----
        {
            const int sel = t >> 7, q = t & 127;
            const int crg = q >> 2, ccg = q & 3;
            const float* Sh = sm + (hsel ? O_S1 : O_S0);
            const int bcol = h * DK + 4 * ccg;
            u64 acc[2][2] = {{0ull, 0ull}, {0ull, 0ull}};
            if (sel == 0) {
#pragma unroll 4
                for (int kk = 0; kk < 16; ++kk) {
                    float4 s0 = *reinterpret_cast<const float4*>(Sh + (2 * crg + 0) * 68 + 4 * kk);
                    float4 s1 = *reinterpret_cast<const float4*>(Sh + (2 * crg + 1) * 68 + 4 * kk);
                    float s0v[4] = {s0.x, s0.y, s0.z, s0.w};
                    float s1v[4] = {s1.x, s1.y, s1.z, s1.w};
#pragma unroll
                    for (int j = 0; j < 4; j++) {
                        float4 b = *reinterpret_cast<const float4*>(
                            sm + O_V + (4 * kk + j) * 128 + bcol);
                        u64 b0 = pk2(b.x, b.y), b1 = pk2(b.z, b.w);
                        u64 a0 = dup2(s0v[j]), a1 = dup2(s1v[j]);
                        fma2(acc[0][0], a0, b0); fma2(acc[0][1], a0, b1);
                        fma2(acc[1][0], a1, b0); fma2(acc[1][1], a1, b1);
                    }
                }
            } else {
#pragma unroll 4
                for (int kk = 0; kk < 16; ++kk) {
                    float4 s0 = *reinterpret_cast<const float4*>(Sh + (2 * crg + 0) * 68 + 4 * kk);
                    float4 s1 = *reinterpret_cast<const float4*>(Sh + (2 * crg + 1) * 68 + 4 * kk);
                    float s0v[4] = {s0.x, s0.y, s0.z, s0.w};
                    float s1v[4] = {s1.x, s1.y, s1.z, s1.w};
#pragma unroll
                    for (int j = 0; j < 4; j++) {
                        float4 b = __ldg(reinterpret_cast<const float4*>(
                            xt_src + (4 * kk + j) * D + bcol));
                        u64 b0 = pk2(b.x, b.y), b1 = pk2(b.z, b.w);
                        u64 a0 = dup2(s0v[j]), a1 = dup2(s1v[j]);
                        fma2(acc[0][0], a0, b0); fma2(acc[0][1], a0, b1);
                        fma2(acc[1][0], a1, b0); fma2(acc[1][1], a1, b1);
                    }
                }
            }
            float* dst = sel ? (sm + O_XK) : (sm + O_Q);   // CTB(132) : TVB(128)
            const int ds = sel ? 132 : 128;
#pragma unroll
            for (int i = 0; i < 2; i++) {
                float2 p0 = upk(acc[i][0]), p1 = upk(acc[i][1]);
                *reinterpret_cast<float4*>(dst + (2 * crg + i) * ds + bcol) =
                    make_float4(p0.x, p0.y, p1.x, p1.y);
            }
        }
        half_bar(hsel);
    }
    __syncthreads();   // both halves done before WB overlays S

    // ================= epilogue: projection + LayerNorm x2 (pipelined W) =====
    stage_w(WB0, Wot, tid);
    stage_w(WB1, Wot + 8192, tid);

    u64 accE[4][2];
    float vals[4][4];
    float4 gv, bv2;

    // ---- time branch: TVB @ Wot + bot + residual, LN ----
    cpa_wait<1>(); __syncthreads();
    {
        float4 bb = __ldg(reinterpret_cast<const float4*>(bot + c0e));
        u64 b0 = pk2(bb.x, bb.y), b1 = pk2(bb.z, bb.w);
#pragma unroll
        for (int i = 0; i < 4; i++) { accE[i][0] = b0; accE[i][1] = b1; }
    }
    hg44<128>(sm + O_Q, WB0, r0e, c0e, 0, accE);
    __syncthreads();
    stage_w(WB0, Wtg, tid);
    cpa_wait<1>(); __syncthreads();
    hg44<128>(sm + O_Q, WB1, r0e, c0e, 64, accE);
#pragma unroll
    for (int i = 0; i < 4; i++) {
        float2 p0 = upk(accE[i][0]), p1 = upk(accE[i][1]);
        float4 x = *reinterpret_cast<const float4*>(sm + O_XQ + (r0e + i) * 132 + c0e);
        vals[i][0] = p0.x + x.x; vals[i][1] = p0.y + x.y;
        vals[i][2] = p1.x + x.z; vals[i][3] = p1.y + x.w;
    }
    gv  = __ldg(reinterpret_cast<const float4*>(g_time + c0e));
    bv2 = __ldg(reinterpret_cast<const float4*>(b_time + c0e));
#pragma unroll
    for (int i = 0; i < 4; i++) {
        float s1 = vals[i][0] + vals[i][1] + vals[i][2] + vals[i][3];
        float s2 = vals[i][0]*vals[i][0] + vals[i][1]*vals[i][1]
                 + vals[i][2]*vals[i][2] + vals[i][3]*vals[i][3];
#pragma unroll
        for (int o = 16; o; o >>= 1) {
            s1 += __shfl_xor_sync(0xffffffffu, s1, o);
            s2 += __shfl_xor_sync(0xffffffffu, s2, o);
        }
        float mean = s1 * (1.0f / 128.0f);
        float var  = s2 * (1.0f / 128.0f) - mean * mean;
        float rstd = rsqrtf(var + 1e-5f);
        float4 y;
        y.x = (vals[i][0] - mean) * rstd * gv.x + bv2.x;
        y.y = (vals[i][1] - mean) * rstd * gv.y + bv2.y;
        y.z = (vals[i][2] - mean) * rstd * gv.z + bv2.z;
        y.w = (vals[i][3] - mean) * rstd * gv.w + bv2.w;
        *reinterpret_cast<float4*>(tv_base + (r0e + i) * D + c0e) = y;
    }
    __syncthreads();
    stage_w(WB1, Wtg + 8192, tid);

    // ---- target branch: CTB @ Wtg + btg, LN ----
    cpa_wait<1>(); __syncthreads();
    {
        float4 bb = __ldg(reinterpret_cast<const float4*>(btg + c0e));
        u64 b0 = pk2(bb.x, bb.y), b1 = pk2(bb.z, bb.w);
#pragma unroll
        for (int i = 0; i < 4; i++) { accE[i][0] = b0; accE[i][1] = b1; }
    }
    hg44<132>(sm + O_XK, WB0, r0e, c0e, 0, accE);
    cpa_wait<0>(); __syncthreads();
    hg44<132>(sm + O_XK, WB1, r0e, c0e, 64, accE);
#pragma unroll
    for (int i = 0; i < 4; i++) {
        float2 p0 = upk(accE[i][0]), p1 = upk(accE[i][1]);
        vals[i][0] = p0.x; vals[i][1] = p0.y; vals[i][2] = p1.x; vals[i][3] = p1.y;
    }
    gv  = __ldg(reinterpret_cast<const float4*>(g_tgt + c0e));
    bv2 = __ldg(reinterpret_cast<const float4*>(b_tgt + c0e));
#pragma unroll
    for (int i = 0; i < 4; i++) {
        float s1 = vals[i][0] + vals[i][1] + vals[i][2] + vals[i][3];
        float s2 = vals[i][0]*vals[i][0] + vals[i][1]*vals[i][1]
                 + vals[i][2]*vals[i][2] + vals[i][3]*vals[i][3];
#pragma unroll
        for (int o = 16; o; o >>= 1) {
            s1 += __shfl_xor_sync(0xffffffffu, s1, o);
            s2 += __shfl_xor_sync(0xffffffffu, s2, o);
        }
        float mean = s1 * (1.0f / 128.0f);
        float var  = s2 * (1.0f / 128.0f) - mean * mean;
        float rstd = rsqrtf(var + 1e-5f);
        float4 y;
        y.x = (vals[i][0] - mean) * rstd * gv.x + bv2.x;
        y.y = (vals[i][1] - mean) * rstd * gv.y + bv2.y;
        y.z = (vals[i][2] - mean) * rstd * gv.z + bv2.z;
        y.w = (vals[i][3] - mean) * rstd * gv.w + bv2.w;
        *reinterpret_cast<float4*>(ct_base + (r0e + i) * D + c0e) = y;
    }
}

extern "C" void kernel_launch(void* const* d_in, const int* in_sizes, int n_in,
                              void* d_out, int out_size) {
    const float* xq  = (const float*)d_in[0];
    const float* xk  = (const float*)d_in[1];
    const float* xt  = (const float*)d_in[2];
    const float* Wq  = (const float*)d_in[3];
    const float* bq  = (const float*)d_in[4];
    const float* Wk  = (const float*)d_in[5];
    const float* bk  = (const float*)d_in[6];
    const float* Wv  = (const float*)d_in[7];
    const float* bv  = (const float*)d_in[8];
    const float* Wot = (const float*)d_in[9];
    const float* bot = (const float*)d_in[10];
    const float* Wtg = (const float*)d_in[11];
    const float* btg = (const float*)d_in[12];
    const float* g_time = (const float*)d_in[13];
    const float* b_time = (const float*)d_in[14];
    const float* g_tgt  = (const float*)d_in[15];
    const float* b_tgt  = (const float*)d_in[16];
    float* out = (float*)d_out;

    int BN = in_sizes[0] / (L * D);

    cudaFuncSetAttribute(fused_attn_kernel,
                         cudaFuncAttributeMaxDynamicSharedMemorySize, SM_BYTES);
    fused_attn_kernel<<<BN, NT, SM_BYTES>>>(
        xq, xk, xt, Wq, bq, Wk, bk, Wv, bv, Wot, bot, Wtg, btg,
        g_time, b_time, g_tgt, b_tgt, out, BN);
}

// round 11
// speedup vs baseline: 1.3087x; 1.3087x over previous
#include <cuda_runtime.h>
#include <cuda_bf16.h>

#define NT 512
typedef unsigned long long u64;
typedef unsigned int u32;
typedef unsigned short u16;

static constexpr int L = 64, D = 128, H = 8, DK = 16;

// ---- byte offsets (bf16 staging regions) ----
static constexpr int B_AKHI = 0;        // xk hi  [64][136] bf16 (17408B)
static constexpr int B_AKLO = 17408;    // xk lo
static constexpr int B_AQHI = 34816;    // xq hi
static constexpr int B_AQLO = 52224;    // xq lo
static constexpr int B_WHI  = 69632;    // W^T hi [128][136] bf16 (34816B)
static constexpr int B_WLO  = 104448;   // W^T lo
static constexpr int B_EAHI = 139264;   // epilogue A hi [64][136]
static constexpr int B_EALO = 156672;   // epilogue A lo
// ---- float offsets (f32 views; time-disjoint overlays with the above) ----
static constexpr int O_CTB = 0;      // [64][128] CT buffer      (overlays AK)
static constexpr int O_Q   = 8704;   // [64][128] Q -> TVB       (overlays AQ)
static constexpr int O_S0  = 17408;  // [64][68]                 (overlays W)
static constexpr int O_S1  = 21760;  //                          (overlays W)
static constexpr int O_XTS = 26112;  // [64][32]                 (overlays W)
static constexpr int O_KT  = 34816;  // [128][68] K^T rotated    (overlays EA)
static constexpr int O_V   = 43520;  // [64][128] V; epilogue out
static constexpr int SM_FLOATS = 51712;
static constexpr int SM_BYTES  = SM_FLOATS * 4;   // 206848

// ---------------- helpers ----------------
static __device__ __forceinline__ u64 pk2(float lo, float hi) {
    u64 r; asm("mov.b64 %0,{%1,%2};" : "=l"(r) : "f"(lo), "f"(hi)); return r;
}
static __device__ __forceinline__ u64 dup2(float v) {
    u64 r; asm("mov.b64 %0,{%1,%1};" : "=l"(r) : "f"(v)); return r;
}
static __device__ __forceinline__ void fma2(u64& d, u64 a, u64 b) {
    asm("fma.rn.f32x2 %0, %1, %2, %0;" : "+l"(d) : "l"(a), "l"(b));
}
static __device__ __forceinline__ float2 upk(u64 v) {
    float lo, hi; asm("mov.b64 {%0,%1}, %2;" : "=f"(lo), "=f"(hi) : "l"(v));
    return make_float2(lo, hi);
}
static __device__ __forceinline__ void ldsm4(u32* r, u32 addr) {
    asm volatile("ldmatrix.sync.aligned.m8n8.x4.shared.b16 {%0,%1,%2,%3}, [%4];"
        : "=r"(r[0]), "=r"(r[1]), "=r"(r[2]), "=r"(r[3]) : "r"(addr));
}
static __device__ __forceinline__ void mmabf(float* d, const u32* a, u32 b0, u32 b1) {
    asm volatile("mma.sync.aligned.m16n8k16.row.col.f32.bf16.bf16.f32 "
        "{%0,%1,%2,%3}, {%4,%5,%6,%7}, {%8,%9}, {%0,%1,%2,%3};"
        : "+f"(d[0]), "+f"(d[1]), "+f"(d[2]), "+f"(d[3])
        : "r"(a[0]), "r"(a[1]), "r"(a[2]), "r"(a[3]), "r"(b0), "r"(b1));
}
static __device__ __forceinline__ void bsplit4(float4 v, u64& hi, u64& lo) {
    u16 h[4], l[4];
    float x[4] = {v.x, v.y, v.z, v.w};
#pragma unroll
    for (int i = 0; i < 4; i++) {
        __nv_bfloat16 bh = __float2bfloat16(x[i]);
        h[i] = __bfloat16_as_ushort(bh);
        l[i] = __bfloat16_as_ushort(__float2bfloat16(x[i] - __bfloat162float(bh)));
    }
    hi = (u64)h[0] | ((u64)h[1] << 16) | ((u64)h[2] << 32) | ((u64)h[3] << 48);
    lo = (u64)l[0] | ((u64)l[1] << 16) | ((u64)l[2] << 32) | ((u64)l[3] << 48);
}

// 3-pass bf16-split GEMM: warp tile 16m x 32n, K=128. A/W smem stride 272B.
static __device__ __forceinline__ void gemm3(u32 sb, u32 aHi, u32 aLo,
                                             int lane, int m0, int n0, float d[16]) {
    const u32 aoff = (u32)((m0 + (lane & 15)) * 272 + (lane >> 4) * 16);
    const u32 brow = (u32)(((lane & 7) + ((lane >> 4) << 3)) * 272 + ((lane >> 3) & 1) * 16);
    const u32 b0o = brow + (u32)(n0 * 272);
    const u32 b1o = b0o + 16 * 272;
#pragma unroll
    for (int kk = 0; kk < 8; ++kk) {
        const u32 ka = (u32)(kk * 32);
        u32 ah[4], al[4], bh0[4], bh1[4], bl0[4], bl1[4];
        ldsm4(ah, sb + aHi + aoff + ka);
        ldsm4(al, sb + aLo + aoff + ka);
        ldsm4(bh0, sb + B_WHI + b0o + ka);
        ldsm4(bh1, sb + B_WHI + b1o + ka);
        ldsm4(bl0, sb + B_WLO + b0o + ka);
        ldsm4(bl1, sb + B_WLO + b1o + ka);
#pragma unroll
        for (int t = 0; t < 4; ++t) {
            const u32* bh = (t < 2) ? bh0 : bh1;
            const u32* bl = (t < 2) ? bl0 : bl1;
            const int s = (t & 1) * 2;
            mmabf(d + 4 * t, ah, bh[s], bh[s + 1]);
            mmabf(d + 4 * t, ah, bl[s], bl[s + 1]);
            mmabf(d + 4 * t, al, bh[s], bh[s + 1]);
        }
    }
}

__global__ void __launch_bounds__(NT, 1)
fused_attn_kernel(const float* __restrict__ xq_g, const float* __restrict__ xk_g,
                  const float* __restrict__ xt_g,
                  const float* __restrict__ Wq,  const float* __restrict__ bq,
                  const float* __restrict__ Wk,  const float* __restrict__ bk,
                  const float* __restrict__ Wv,  const float* __restrict__ bv,
                  const float* __restrict__ Wot, const float* __restrict__ bot,
                  const float* __restrict__ Wtg, const float* __restrict__ btg,
                  const float* __restrict__ g_time, const float* __restrict__ b_time,
                  const float* __restrict__ g_tgt,  const float* __restrict__ b_tgt,
                  float* __restrict__ out, int BN)
{
    extern __shared__ float sm[];
    char* smc = reinterpret_cast<char*>(sm);
    const u32 sb = (u32)__cvta_generic_to_shared(sm);
    const int tid = threadIdx.x, bn = blockIdx.x;
    const int wid = tid >> 5, lane = tid & 31;
    const int m0 = 16 * (wid >> 2), n0 = 32 * (wid & 3);

    const float* xq_src = xq_g + (size_t)bn * (L * D);
    const float* xk_src = xk_g + (size_t)bn * (L * D);
    const float* xt_src = xt_g + (size_t)bn * (L * D);

    const size_t attnElems = (size_t)BN * H * (L * L);
    float* tv_base = out + attnElems + (size_t)bn * (L * D);
    float* ct_base = out + attnElems + (size_t)BN * (L * D) + (size_t)bn * (L * D);

    // ---- W^T bf16 hi/lo stager: B[n][k] = W[k][n], stride 272B ----
    auto stageW = [&](const float* W) {
        for (int u = tid; u < 4096; u += NT) {
            int n = u & 127, k0 = 4 * (u >> 7);
            float4 v;
            v.x = __ldg(W + (k0 + 0) * D + n);
            v.y = __ldg(W + (k0 + 1) * D + n);
            v.z = __ldg(W + (k0 + 2) * D + n);
            v.w = __ldg(W + (k0 + 3) * D + n);
            u64 hi, lo; bsplit4(v, hi, lo);
            *reinterpret_cast<u64*>(smc + B_WHI + n * 272 + k0 * 2) = hi;
            *reinterpret_cast<u64*>(smc + B_WLO + n * 272 + k0 * 2) = lo;
        }
    };

    // ---- convert xq, xk to bf16 hi/lo ----
    for (int u = tid; u < 2048; u += NT) {
        int m = u >> 5, k0 = 4 * (u & 31);
        u64 hi, lo;
        bsplit4(__ldg(reinterpret_cast<const float4*>(xq_src + m * D + k0)), hi, lo);
        *reinterpret_cast<u64*>(smc + B_AQHI + m * 272 + k0 * 2) = hi;
        *reinterpret_cast<u64*>(smc + B_AQLO + m * 272 + k0 * 2) = lo;
        bsplit4(__ldg(reinterpret_cast<const float4*>(xk_src + m * D + k0)), hi, lo);
        *reinterpret_cast<u64*>(smc + B_AKHI + m * 272 + k0 * 2) = hi;
        *reinterpret_cast<u64*>(smc + B_AKLO + m * 272 + k0 * 2) = lo;
    }
    stageW(Wq);
    __syncthreads();

    const int r1 = m0 + (lane >> 2), cb = 2 * (lane & 3);

    // ================= Q = xq @ Wq + bq =================
    {
        float d[16] = {0,0,0,0,0,0,0,0,0,0,0,0,0,0,0,0};
        gemm3(sb, B_AQHI, B_AQLO, lane, m0, n0, d);
        __syncthreads();              // all AQ/W reads done before overwrite/restage
#pragma unroll
        for (int t = 0; t < 4; ++t) {
            int c = n0 + 8 * t + cb;
            float2 bb = __ldg(reinterpret_cast<const float2*>(bq + c));
            *reinterpret_cast<float2*>(sm + O_Q + r1 * 128 + c) =
                make_float2(d[4*t] + bb.x, d[4*t+1] + bb.y);
            *reinterpret_cast<float2*>(sm + O_Q + (r1 + 8) * 128 + c) =
                make_float2(d[4*t+2] + bb.x, d[4*t+3] + bb.y);
        }
        stageW(Wk);
    }
    __syncthreads();

    // ================= K = xk @ Wk + bk -> KT[c][rot] =================
    {
        float d[16] = {0,0,0,0,0,0,0,0,0,0,0,0,0,0,0,0};
        gemm3(sb, B_AKHI, B_AKLO, lane, m0, n0, d);
        __syncthreads();
#pragma unroll
        for (int t = 0; t < 4; ++t) {
            int c = n0 + 8 * t + cb;
            float b0 = __ldg(bk + c), b1 = __ldg(bk + c + 1);
            int ro0 = (4 * (c >> 1)) & 63, ro1 = (4 * ((c + 1) >> 1)) & 63;
            sm[O_KT + c * 68 + ((r1 + ro0) & 63)]       = d[4*t]   + b0;
            sm[O_KT + (c+1) * 68 + ((r1 + ro1) & 63)]   = d[4*t+1] + b1;
            sm[O_KT + c * 68 + ((r1 + 8 + ro0) & 63)]   = d[4*t+2] + b0;
            sm[O_KT + (c+1) * 68 + ((r1 + 8 + ro1) & 63)] = d[4*t+3] + b1;
        }
        stageW(Wv);
    }
    __syncthreads();

    // ================= V = xk @ Wv + bv =================
    {
        float d[16] = {0,0,0,0,0,0,0,0,0,0,0,0,0,0,0,0};
        gemm3(sb, B_AKHI, B_AKLO, lane, m0, n0, d);
        __syncthreads();
#pragma unroll
        for (int t = 0; t < 4; ++t) {
            int c = n0 + 8 * t + cb;
            float2 bb = __ldg(reinterpret_cast<const float2*>(bv + c));
            *reinterpret_cast<float2*>(sm + O_V + r1 * 128 + c) =
                make_float2(d[4*t] + bb.x, d[4*t+1] + bb.y);
            *reinterpret_cast<float2*>(sm + O_V + (r1 + 8) * 128 + c) =
                make_float2(d[4*t+2] + bb.x, d[4*t+3] + bb.y);
        }
    }
    __syncthreads();

    // ================= middle: per head-pair scores + apply (R8 FFMA path) ===
    const int t8 = tid & 255, hsel = tid >> 8;
#pragma unroll 1
    for (int p = 0; p < 4; ++p) {
        const int h = 2 * p + hsel, hcol = h * DK;
        // stage target cols of this pair: xts[k][0..31] = xt[k][32p..32p+31]
        {
            int k = tid >> 3, c4 = tid & 7;
            reinterpret_cast<float4*>(sm + O_XTS)[tid] =
                __ldg(reinterpret_cast<const float4*>(xt_src + k * D + p * 32 + 4 * c4));
        }
        // ---- S_h = Q_h @ K_h^T * 0.25 ----
        {
            const int brg = t8 >> 4, bcg = t8 & 15;
            u64 acc[4][2];
#pragma unroll
            for (int i = 0; i < 4; i++) acc[i][0] = acc[i][1] = 0ull;
#pragma unroll
            for (int kk = 0; kk < 4; ++kk) {
                float av[4][4];
#pragma unroll
                for (int i = 0; i < 4; i++) {
                    float4 a = *reinterpret_cast<const float4*>(
                        sm + O_Q + (4 * brg + i) * 128 + hcol + 4 * kk);
                    av[i][0] = a.x; av[i][1] = a.y; av[i][2] = a.z; av[i][3] = a.w;
                }
#pragma unroll
                for (int j = 0; j < 4; j++) {
                    int c = hcol + 4 * kk + j;
                    int rot = (4 * (c >> 1)) & 63;
                    float4 b = *reinterpret_cast<const float4*>(
                        sm + O_KT + c * 68 + ((4 * bcg + rot) & 63));
                    u64 b0 = pk2(b.x, b.y), b1 = pk2(b.z, b.w);
#pragma unroll
                    for (int i = 0; i < 4; i++) {
                        u64 ad = dup2(av[i][j]);
                        fma2(acc[i][0], ad, b0);
                        fma2(acc[i][1], ad, b1);
                    }
                }
            }
            float* Sh = sm + (hsel ? O_S1 : O_S0);
            float* attn = out + ((size_t)bn * H + h) * (L * L);
#pragma unroll
            for (int i = 0; i < 4; i++) {
                float2 p0 = upk(acc[i][0]), p1 = upk(acc[i][1]);
                float4 v = make_float4(p0.x * 0.25f, p0.y * 0.25f, p1.x * 0.25f, p1.y * 0.25f);
                *reinterpret_cast<float4*>(Sh + (4 * brg + i) * 68 + 4 * bcg) = v;
                *reinterpret_cast<float4*>(attn + (4 * brg + i) * L + 4 * bcg) = v;
            }
        }
        __syncthreads();
        // ---- TV_h = S_h @ V_h (sel0 -> O_Q) ; CT_h = S_h @ XT_h (sel1 -> O_CTB) ----
        {
            const int sel = t8 >> 7, q = t8 & 127;
            const int crg = q >> 2, ccg = q & 3;
            const float* Sh = sm + (hsel ? O_S1 : O_S0);
            const float* B = sel ? (sm + O_XTS) : (sm + O_V);
            const int bstride = sel ? 32 : 128;
            const int bcol = sel ? (hsel * DK + 4 * ccg) : (hcol + 4 * ccg);
            u64 acc[2][2] = {{0ull, 0ull}, {0ull, 0ull}};
#pragma unroll 4
            for (int kk = 0; kk < 16; ++kk) {
                float4 s0 = *reinterpret_cast<const float4*>(Sh + (2*crg+0) * 68 + 4*kk);
                float4 s1 = *reinterpret_cast<const float4*>(Sh + (2*crg+1) * 68 + 4*kk);
                float s0v[4] = {s0.x, s0.y, s0.z, s0.w};
                float s1v[4] = {s1.x, s1.y, s1.z, s1.w};
#pragma unroll
                for (int j = 0; j < 4; j++) {
                    float4 b = *reinterpret_cast<const float4*>(B + (4*kk + j) * bstride + bcol);
                    u64 b0 = pk2(b.x, b.y), b1 = pk2(b.z, b.w);
                    u64 a0 = dup2(s0v[j]), a1 = dup2(s1v[j]);
                    fma2(acc[0][0], a0, b0); fma2(acc[0][1], a0, b1);
                    fma2(acc[1][0], a1, b0); fma2(acc[1][1], a1, b1);
                }
            }
            float* dst = sm + (sel ? O_CTB : O_Q);
#pragma unroll
            for (int i = 0; i < 2; i++) {
                float2 p0 = upk(acc[i][0]), p1 = upk(acc[i][1]);
                *reinterpret_cast<float4*>(dst + (2 * crg + i) * 128 + hcol + 4 * ccg) =
                    make_float4(p0.x, p0.y, p1.x, p1.y);
            }
        }
        __syncthreads();
    }

    // ================= epilogue: 2 projections (mma) + LayerNorm =================
#pragma unroll 1
    for (int br = 0; br < 2; ++br) {
        // convert A (TVB in O_Q / CTB in O_CTB) to bf16 hi/lo
        const int asrc = br ? O_CTB : O_Q;
        for (int u = tid; u < 2048; u += NT) {
            int m = u >> 5, k0 = 4 * (u & 31);
            float4 v = *reinterpret_cast<const float4*>(sm + asrc + m * 128 + k0);
            u64 hi, lo; bsplit4(v, hi, lo);
            *reinterpret_cast<u64*>(smc + B_EAHI + m * 272 + k0 * 2) = hi;
            *reinterpret_cast<u64*>(smc + B_EALO + m * 272 + k0 * 2) = lo;
        }
        stageW(br ? Wtg : Wot);
        __syncthreads();

        float d[16] = {0,0,0,0,0,0,0,0,0,0,0,0,0,0,0,0};
        gemm3(sb, B_EAHI, B_EALO, lane, m0, n0, d);
        // raw projection -> O_V region (V dead after middle)
#pragma unroll
        for (int t = 0; t < 4; ++t) {
            int c = n0 + 8 * t + cb;
            *reinterpret_cast<float2*>(sm + O_V + r1 * 128 + c) =
                make_float2(d[4*t], d[4*t+1]);
            *reinterpret_cast<float2*>(sm + O_V + (r1 + 8) * 128 + c) =
                make_float2(d[4*t+2], d[4*t+3]);
        }
        __syncthreads();

        // LN: warp owns rows 4*wid..4*wid+3; bias (+residual) folded in here
        {
            const float* bias = br ? btg : bot;
            const float* gam  = br ? g_tgt : g_time;
            const float* bet  = br ? b_tgt : b_time;
            float* dstg = br ? ct_base : tv_base;
            const int c0 = 4 * lane;
            float4 bb = __ldg(reinterpret_cast<const float4*>(bias + c0));
            float4 gv = __ldg(reinterpret_cast<const float4*>(gam + c0));
            float4 be = __ldg(reinterpret_cast<const float4*>(bet + c0));
#pragma unroll
            for (int i = 0; i < 4; ++i) {
                int r = 4 * wid + i;
                float4 x = *reinterpret_cast<const float4*>(sm + O_V + r * 128 + c0);
                float v0 = x.x + bb.x, v1 = x.y + bb.y, v2 = x.z + bb.z, v3 = x.w + bb.w;
                if (br == 0) {
                    float4 xr = __ldg(reinterpret_cast<const float4*>(xq_src + r * D + c0));
                    v0 += xr.x; v1 += xr.y; v2 += xr.z; v3 += xr.w;
                }
                float s1 = v0 + v1 + v2 + v3;
                float s2 = v0*v0 + v1*v1 + v2*v2 + v3*v3;
#pragma unroll
                for (int o = 16; o; o >>= 1) {
                    s1 += __shfl_xor_sync(0xffffffffu, s1, o);
                    s2 += __shfl_xor_sync(0xffffffffu, s2, o);
                }
                float mean = s1 * (1.0f / 128.0f);
                float var  = s2 * (1.0f / 128.0f) - mean * mean;
                float rstd = rsqrtf(var + 1e-5f);
                float4 y;
                y.x = (v0 - mean) * rstd * gv.x + be.x;
                y.y = (v1 - mean) * rstd * gv.y + be.y;
                y.z = (v2 - mean) * rstd * gv.z + be.z;
                y.w = (v3 - mean) * rstd * gv.w + be.w;
                *reinterpret_cast<float4*>(dstg + r * D + c0) = y;
            }
        }
        __syncthreads();
    }
}

extern "C" void kernel_launch(void* const* d_in, const int* in_sizes, int n_in,
                              void* d_out, int out_size) {
    const float* xq  = (const float*)d_in[0];
    const float* xk  = (const float*)d_in[1];
    const float* xt  = (const float*)d_in[2];
    const float* Wq  = (const float*)d_in[3];
    const float* bq  = (const float*)d_in[4];
    const float* Wk  = (const float*)d_in[5];
    const float* bk  = (const float*)d_in[6];
    const float* Wv  = (const float*)d_in[7];
    const float* bv  = (const float*)d_in[8];
    const float* Wot = (const float*)d_in[9];
    const float* bot = (const float*)d_in[10];
    const float* Wtg = (const float*)d_in[11];
    const float* btg = (const float*)d_in[12];
    const float* g_time = (const float*)d_in[13];
    const float* b_time = (const float*)d_in[14];
    const float* g_tgt  = (const float*)d_in[15];
    const float* b_tgt  = (const float*)d_in[16];
    float* out = (float*)d_out;

    int BN = in_sizes[0] / (L * D);

    cudaFuncSetAttribute(fused_attn_kernel,
                         cudaFuncAttributeMaxDynamicSharedMemorySize, SM_BYTES);
    fused_attn_kernel<<<BN, NT, SM_BYTES>>>(
        xq, xk, xt, Wq, bq, Wk, bk, Wv, bv, Wot, bot, Wtg, btg,
        g_time, b_time, g_tgt, b_tgt, out, BN);
}